// round 3
// baseline (speedup 1.0000x reference)
#include <cuda_runtime.h>

// DigitCapsules dynamic routing, fp32.
// B=128, R=1152, C=32, O=32, I=64, CO=1024.
//
// Pipeline (7 launches, graph-capturable, no allocations):
//   k_uhat : u_hat[b,r,co] = sum_i W[r,co,i] * x[b,r,i]   (f32x2 packed-FMA GEMM)
//   3x { k_route  : fused logits(u.Vacc) -> softmax over C -> partial s per r-chunk
//        k_squash : reduce partials, squash, update Vacc / write final v }
// Logit linearity: b_i = u_hat . (v_0+...+v_{i-1}) => only Vacc is kept, never b.

#define NB 128
#define NR 1152
#define NC 32
#define NO 32
#define NI 64
#define NCO (NC * NO)      // 1024
#define RPC 32             // r's per routing chunk
#define RCH (NR / RPC)     // 36 chunks

// Static device scratch (no cudaMalloc anywhere).
__device__ float g_uhat[(size_t)NB * NR * NCO];    // ~604 MB
__device__ float g_spart[(size_t)NB * RCH * NCO];  // ~18 MB
__device__ float g_vacc[(size_t)NB * NCO];         // 512 KB

// Packed fp32x2 FMA: d.lo += a.lo*b.lo ; d.hi += a.hi*b.hi
__device__ __forceinline__ void fma2(unsigned long long& d,
                                     unsigned long long a,
                                     unsigned long long b) {
    asm("fma.rn.f32x2 %0, %1, %2, %0;" : "+l"(d) : "l"(a), "l"(b));
}

// ---------------------------------------------------------------------------
// K1: u_hat GEMM. Grid (CO/64, R). CTA: one r, 64-co chunk, all 128 b.
// 256 threads, per-thread tile 8b x 4co, accumulators paired along K (f32x2).
// smem: xs[b][k] natural; ws[co][k ^ 2*(co&15)] XOR-swizzled so the
// 16-consecutive-co LDS.64 lane pattern is bank-conflict-free. 48 KB total.
// ---------------------------------------------------------------------------
__global__ void __launch_bounds__(256, 2)
k_uhat(const float* __restrict__ x, const float* __restrict__ W) {
    __shared__ float xs[NB * NI];   // 32768 B
    __shared__ float ws[64 * NI];   // 16384 B
    const int r = blockIdx.y;
    const int cobase = blockIdx.x * 64;
    const int tid = threadIdx.x;

    // x[:, r, :] -> xs[b*64 + i]  (coalesced loads, conflict-free stores)
    for (int idx = tid; idx < NB * NI; idx += 256) {
        int b = idx >> 6, i = idx & 63;
        xs[idx] = x[((size_t)b * NR + r) * NI + i];
    }
    // W[r, cobase..+63, :] -> ws, XOR-swizzled along k
    for (int idx = tid; idx < 64 * NI; idx += 256) {
        int co = idx >> 6, i = idx & 63;
        ws[(co << 6) | (i ^ ((co & 15) << 1))] =
            W[((size_t)r * NCO + cobase + co) * NI + i];
    }
    __syncthreads();

    const int tx = tid & 15;        // co lane: co = tx + 16*jc
    const int ty = tid >> 4;        // b  lane: b  = ty + 16*jb
    const int swz = tx << 1;

    unsigned long long acc[8][4];
#pragma unroll
    for (int jb = 0; jb < 8; jb++)
#pragma unroll
        for (int jc = 0; jc < 4; jc++) acc[jb][jc] = 0ull;

#pragma unroll 4
    for (int k = 0; k < NI; k += 2) {
        unsigned long long xp[8], wp[4];
#pragma unroll
        for (int jb = 0; jb < 8; jb++)
            xp[jb] = *(const unsigned long long*)&xs[((ty + (jb << 4)) << 6) + k];
        const int kk = k ^ swz;
#pragma unroll
        for (int jc = 0; jc < 4; jc++)
            wp[jc] = *(const unsigned long long*)&ws[((tx + (jc << 4)) << 6) + kk];
#pragma unroll
        for (int jb = 0; jb < 8; jb++)
#pragma unroll
            for (int jc = 0; jc < 4; jc++)
                fma2(acc[jb][jc], xp[jb], wp[jc]);
    }

#pragma unroll
    for (int jb = 0; jb < 8; jb++) {
        const int b = ty + (jb << 4);
        float* orow = &g_uhat[((size_t)b * NR + r) * NCO + cobase];
#pragma unroll
        for (int jc = 0; jc < 4; jc++) {
            unsigned long long a = acc[jb][jc];
            float lo = __uint_as_float((unsigned)a);
            float hi = __uint_as_float((unsigned)(a >> 32));
            orow[tx + (jc << 4)] = lo + hi;
        }
    }
}

// ---------------------------------------------------------------------------
// K2: fused routing pass. Grid (B, RCH). CTA: one b, RPC r's.
// Thread t owns co quad 4t..4t+3 (c = t>>3). Per r: logit a[c] = u.Vacc
// (8-lane shfl reduce), softmax over C=32 (warp 0), acc += w[c]*u.
// first==1 -> uniform weights 1/32 (softmax of zeros), no barriers needed.
// ---------------------------------------------------------------------------
__global__ void __launch_bounds__(256)
k_route(int first) {
    const int b = blockIdx.x;
    const int ch = blockIdx.y;
    const int t = threadIdx.x;
    __shared__ float sm_a[NC];
    __shared__ float sm_w[NC];

    const float4* up =
        (const float4*)g_uhat + ((size_t)b * NR + ch * RPC) * (NCO / 4) + t;
    float4 vv = make_float4(0.f, 0.f, 0.f, 0.f);
    if (!first) vv = ((const float4*)g_vacc)[b * (NCO / 4) + t];

    float4 acc = make_float4(0.f, 0.f, 0.f, 0.f);
    for (int rr = 0; rr < RPC; rr++) {
        float4 u = up[(size_t)rr * (NCO / 4)];
        float wgt;
        if (first) {
            wgt = 1.0f / 32.0f;
        } else {
            float p = u.x * vv.x + u.y * vv.y + u.z * vv.z + u.w * vv.w;
            p += __shfl_xor_sync(0xffffffffu, p, 1);
            p += __shfl_xor_sync(0xffffffffu, p, 2);
            p += __shfl_xor_sync(0xffffffffu, p, 4);
            if ((t & 7) == 0) sm_a[t >> 3] = p;
            __syncthreads();
            if (t < 32) {
                float av = sm_a[t];
                float mx = av;
#pragma unroll
                for (int s = 16; s; s >>= 1)
                    mx = fmaxf(mx, __shfl_xor_sync(0xffffffffu, mx, s));
                float e = __expf(av - mx);
                float sum = e;
#pragma unroll
                for (int s = 16; s; s >>= 1)
                    sum += __shfl_xor_sync(0xffffffffu, sum, s);
                sm_w[t] = e / sum;
            }
            __syncthreads();
            wgt = sm_w[t >> 3];
        }
        acc.x = fmaf(wgt, u.x, acc.x);
        acc.y = fmaf(wgt, u.y, acc.y);
        acc.z = fmaf(wgt, u.z, acc.z);
        acc.w = fmaf(wgt, u.w, acc.w);
    }
    ((float4*)g_spart)[((size_t)b * RCH + ch) * (NCO / 4) + t] = acc;
}

// ---------------------------------------------------------------------------
// K3: reduce partial s over chunks, squash per (b,c), update Vacc / output.
// Grid (B), 256 threads; thread t owns co quad 4t..4t+3, c = t>>3 => each
// group of 8 lanes covers one c (O=32 values).
// ---------------------------------------------------------------------------
__global__ void __launch_bounds__(256)
k_squash(float* __restrict__ out, int iter) {
    const int b = blockIdx.x;
    const int t = threadIdx.x;

    float4 s = make_float4(0.f, 0.f, 0.f, 0.f);
    const float4* sp = (const float4*)g_spart + (size_t)b * RCH * (NCO / 4) + t;
#pragma unroll 4
    for (int ch = 0; ch < RCH; ch++) {
        float4 p = sp[(size_t)ch * (NCO / 4)];
        s.x += p.x; s.y += p.y; s.z += p.z; s.w += p.w;
    }

    float ss = s.x * s.x + s.y * s.y + s.z * s.z + s.w * s.w;
    ss += __shfl_xor_sync(0xffffffffu, ss, 1);
    ss += __shfl_xor_sync(0xffffffffu, ss, 2);
    ss += __shfl_xor_sync(0xffffffffu, ss, 4);
    float norm = sqrtf(ss);
    float scale = ss / (1.0f + ss) / (norm + 1e-8f);
    float4 v = make_float4(s.x * scale, s.y * scale, s.z * scale, s.w * scale);

    float4* va = (float4*)g_vacc + b * (NCO / 4) + t;
    if (iter == 2) {
        ((float4*)out)[b * (NCO / 4) + t] = v;     // final v -> output [B,C,O]
    } else if (iter == 0) {
        *va = v;                                   // Vacc = v0 (no stale read)
    } else {
        float4 a = *va;
        a.x += v.x; a.y += v.y; a.z += v.z; a.w += v.w;
        *va = a;                                   // Vacc += v1
    }
}

extern "C" void kernel_launch(void* const* d_in, const int* in_sizes, int n_in,
                              void* d_out, int out_size) {
    const float* x = (const float*)d_in[0];  // [B, R, I]
    const float* W = (const float*)d_in[1];  // [R, C, O, I]
    float* out = (float*)d_out;              // [B, C, O]

    k_uhat<<<dim3(NCO / 64, NR), 256>>>(x, W);
    for (int it = 0; it < 3; it++) {
        k_route<<<dim3(NB, RCH), 256>>>(it == 0 ? 1 : 0);
        k_squash<<<NB, 256>>>(out, it);
    }
}